// round 1
// baseline (speedup 1.0000x reference)
#include <cuda_runtime.h>
#include <cstdint>
#include <cstring>

#define N_NODES 50000
#define N_EDGES 800000
#define D_IN 128
#define D_HID 256
#define D_OUT 128

// ---------------- scratch (static device arrays; no allocation) ----------------
__device__ float g_agg1[(size_t)N_NODES * D_IN];   // 25.6 MB  agg of layer-1 input
__device__ float g_h1[(size_t)N_NODES * D_HID];    // 51.2 MB  relu(agg1@W1+b1)
__device__ float g_t2[(size_t)N_NODES * D_OUT];    // 25.6 MB  h1@W2 (pre-agg)

// ---------------- helpers ----------------
__device__ __forceinline__ void red_add_v4(float* p, float4 v) {
    asm volatile("red.global.add.v4.f32 [%0], {%1, %2, %3, %4};"
                 :: "l"(p), "f"(v.x), "f"(v.y), "f"(v.z), "f"(v.w)
                 : "memory");
}

// ---------------- zero fill ----------------
__global__ void zero_buf(float4* __restrict__ p, int n4) {
    int i = blockIdx.x * blockDim.x + threadIdx.x;
    if (i < n4) p[i] = make_float4(0.f, 0.f, 0.f, 0.f);
}

// ---------------- edge aggregation, layer 1 ----------------
// One warp per edge. Gather emb[cncpt[src]] (512B row, L2-hot working set 25.6MB),
// vector-reduce into agg1[dst].
__global__ __launch_bounds__(256) void edge_agg1(
    const int* __restrict__ src, const int* __restrict__ dst,
    const int* __restrict__ cncpt, const float* __restrict__ emb)
{
    int e = (blockIdx.x * blockDim.x + threadIdx.x) >> 5;
    if (e >= N_EDGES) return;
    int lane = threadIdx.x & 31;
    int s = src[e];
    int d = dst[e];
    int row = cncpt[s];
    float4 v = ((const float4*)(emb + (size_t)row * D_IN))[lane];
    red_add_v4(g_agg1 + (size_t)d * D_IN + lane * 4, v);
}

// ---------------- edge aggregation, layer 2 ----------------
// Aggregate t2 = h1@W2 (GEMM commuted before aggregation: width 128, not 256).
__global__ __launch_bounds__(256) void edge_agg2(
    const int* __restrict__ src, const int* __restrict__ dst,
    float* __restrict__ out)
{
    int e = (blockIdx.x * blockDim.x + threadIdx.x) >> 5;
    if (e >= N_EDGES) return;
    int lane = threadIdx.x & 31;
    int s = src[e];
    int d = dst[e];
    float4 v = ((const float4*)(g_t2 + (size_t)s * D_OUT))[lane];
    red_add_v4(out + (size_t)d * D_OUT + lane * 4, v);
}

// ---------------- SIMT fp32 GEMM with packed f32x2 FMA ----------------
// C[M,NDIM] = A[M,KDIM] @ B[KDIM,NDIM]  (+bias, relu if EPI)
// BM=128, BN=64, BK=16, TM=8, TN=4 (2 f32x2 pairs), 256 threads.
template<int KDIM, int NDIM, bool EPI>
__global__ __launch_bounds__(256) void gemm_kernel(
    const float* __restrict__ A, const float* __restrict__ B,
    const float* __restrict__ bias, float* __restrict__ C, int M)
{
    constexpr int BM = 128, BN = 64, BK = 16, TM = 8;
    __shared__ float As[BK][BM + 4];
    __shared__ float Bs[BK][BN];

    const int tid = threadIdx.x;
    const int blockM = blockIdx.y * BM;
    const int blockN = blockIdx.x * BN;

    const int ty = tid >> 4;        // 0..15
    const int tx = tid & 15;        // 0..15
    const int tm0 = ty * TM;
    const int tn0 = tx * 4;

    unsigned long long acc[TM][2];
#pragma unroll
    for (int i = 0; i < TM; i++) { acc[i][0] = 0ull; acc[i][1] = 0ull; }

    for (int k0 = 0; k0 < KDIM; k0 += BK) {
        // load A tile (BM x BK), store transposed As[k][m]
#pragma unroll
        for (int i = 0; i < 2; i++) {
            int f  = tid + i * 256;         // 0..511
            int m  = f >> 2;                // 0..127
            int kq = (f & 3) * 4;           // 0,4,8,12
            int gm = blockM + m;
            float4 v = make_float4(0.f, 0.f, 0.f, 0.f);
            if (gm < M)
                v = *(const float4*)(A + (size_t)gm * KDIM + k0 + kq);
            As[kq + 0][m] = v.x;
            As[kq + 1][m] = v.y;
            As[kq + 2][m] = v.z;
            As[kq + 3][m] = v.w;
        }
        // load B tile (BK x BN): 16*64/4 = 256 float4, one per thread
        {
            int k  = tid >> 4;              // 0..15
            int nq = (tid & 15) * 4;        // 0..60
            *(float4*)&Bs[k][nq] =
                *(const float4*)(B + (size_t)(k0 + k) * NDIM + blockN + nq);
        }
        __syncthreads();

#pragma unroll
        for (int k = 0; k < BK; k++) {
            float a[TM];
            *(float4*)&a[0] = *(const float4*)&As[k][tm0];
            *(float4*)&a[4] = *(const float4*)&As[k][tm0 + 4];
            unsigned long long b0 = *(const unsigned long long*)&Bs[k][tn0];
            unsigned long long b1 = *(const unsigned long long*)&Bs[k][tn0 + 2];
#pragma unroll
            for (int i = 0; i < TM; i++) {
                unsigned long long a2;
                asm("mov.b64 %0, {%1, %1};" : "=l"(a2) : "f"(a[i]));
                asm("fma.rn.f32x2 %0, %1, %2, %3;"
                    : "=l"(acc[i][0]) : "l"(a2), "l"(b0), "l"(acc[i][0]));
                asm("fma.rn.f32x2 %0, %1, %2, %3;"
                    : "=l"(acc[i][1]) : "l"(a2), "l"(b1), "l"(acc[i][1]));
            }
        }
        __syncthreads();
    }

    float bs[4] = {0.f, 0.f, 0.f, 0.f};
    if (EPI) {
#pragma unroll
        for (int j = 0; j < 4; j++) bs[j] = bias[blockN + tn0 + j];
    }

#pragma unroll
    for (int i = 0; i < TM; i++) {
        int gm = blockM + tm0 + i;
        if (gm >= M) continue;
        float2 lo, hi;
        memcpy(&lo, &acc[i][0], 8);
        memcpy(&hi, &acc[i][1], 8);
        float4 o = make_float4(lo.x, lo.y, hi.x, hi.y);
        if (EPI) {
            o.x = fmaxf(o.x + bs[0], 0.f);
            o.y = fmaxf(o.y + bs[1], 0.f);
            o.z = fmaxf(o.z + bs[2], 0.f);
            o.w = fmaxf(o.w + bs[3], 0.f);
        }
        *(float4*)(C + (size_t)gm * NDIM + blockN + tn0) = o;
    }
}

// ---------------- final epilogue: out = relu(out + b2) ----------------
__global__ void bias_relu_out(float* __restrict__ out, const float* __restrict__ b) {
    int i = blockIdx.x * blockDim.x + threadIdx.x;
    const int n4 = N_NODES * D_OUT / 4;
    if (i >= n4) return;
    float4 v = ((float4*)out)[i];
    int n = (i * 4) & (D_OUT - 1);
    v.x = fmaxf(v.x + b[n + 0], 0.f);
    v.y = fmaxf(v.y + b[n + 1], 0.f);
    v.z = fmaxf(v.z + b[n + 2], 0.f);
    v.w = fmaxf(v.w + b[n + 3], 0.f);
    ((float4*)out)[i] = v;
}

// ---------------- launch ----------------
extern "C" void kernel_launch(void* const* d_in, const int* in_sizes, int n_in,
                              void* d_out, int out_size) {
    const int*   cncpt = (const int*)d_in[0];
    const int*   src   = (const int*)d_in[1];
    const int*   dst   = (const int*)d_in[2];
    const float* emb   = (const float*)d_in[3];
    const float* W1    = (const float*)d_in[4];
    const float* b1    = (const float*)d_in[5];
    const float* W2    = (const float*)d_in[6];
    const float* b2    = (const float*)d_in[7];
    float* out = (float*)d_out;

    float *agg1, *h1, *t2;
    cudaGetSymbolAddress((void**)&agg1, g_agg1);
    cudaGetSymbolAddress((void**)&h1,  g_h1);
    cudaGetSymbolAddress((void**)&t2,  g_t2);

    const int edge_blocks = (N_EDGES * 32 + 255) / 256;   // one warp per edge

    // layer 1: zero agg1; scatter-sum emb[cncpt[src]] into agg1[dst]
    {
        int n4 = N_NODES * D_IN / 4;
        zero_buf<<<(n4 + 255) / 256, 256>>>((float4*)agg1, n4);
    }
    edge_agg1<<<edge_blocks, 256>>>(src, dst, cncpt, emb);

    // h1 = relu(agg1 @ W1 + b1)   [50000 x 256], K=128
    {
        dim3 grid(D_HID / 64, (N_NODES + 127) / 128);
        gemm_kernel<D_IN, D_HID, true><<<grid, 256>>>(agg1, W1, b1, h1, N_NODES);
    }

    // t2 = h1 @ W2   [50000 x 128], K=256   (GEMM commuted before aggregation)
    {
        dim3 grid(D_OUT / 64, (N_NODES + 127) / 128);
        gemm_kernel<D_HID, D_OUT, false><<<grid, 256>>>(h1, W2, nullptr, t2, N_NODES);
    }

    // layer 2: zero d_out; scatter-sum t2[src] into out[dst]; then +b2, relu
    {
        int n4 = N_NODES * D_OUT / 4;
        zero_buf<<<(n4 + 255) / 256, 256>>>((float4*)out, n4);
    }
    edge_agg2<<<edge_blocks, 256>>>(src, dst, out);
    bias_relu_out<<<(N_NODES * D_OUT / 4 + 255) / 256, 256>>>(out, b2);
}

// round 2
// speedup vs baseline: 1.1258x; 1.1258x over previous
#include <cuda_runtime.h>
#include <cstdint>
#include <cstring>

#define N_NODES 50000
#define N_EDGES 800000
#define D_IN 128
#define D_HID 256
#define D_OUT 128

// ---------------- scratch (static device arrays; no allocation) ----------------
__device__ float g_agg1[(size_t)N_NODES * D_IN];   // 25.6 MB
__device__ float g_h1[(size_t)N_NODES * D_HID];    // 51.2 MB
__device__ float g_t2[(size_t)N_NODES * D_OUT];    // 25.6 MB
__device__ int   g_deg[N_NODES];
__device__ int   g_off[N_NODES + 1];
__device__ int   g_cur[N_NODES];
__device__ int   g_csr_src[N_EDGES];

// ================= CSR build =================
__global__ void zero_deg() {
    int i = blockIdx.x * blockDim.x + threadIdx.x;
    if (i < N_NODES) g_deg[i] = 0;
}

__global__ __launch_bounds__(256) void hist_dst(const int* __restrict__ dst) {
    int e = blockIdx.x * blockDim.x + threadIdx.x;
    if (e < N_EDGES) atomicAdd(&g_deg[dst[e]], 1);
}

// single-block exclusive scan of g_deg -> g_off (and g_cur copy)
__global__ __launch_bounds__(1024) void scan_deg() {
    __shared__ int sums[1024];
    const int CHUNK = (N_NODES + 1023) / 1024;   // 49
    int t = threadIdx.x;
    int lo = t * CHUNK;
    int hi = min(lo + CHUNK, N_NODES);
    int s = 0;
    for (int i = lo; i < hi; i++) s += g_deg[i];
    sums[t] = s;
    __syncthreads();
    // Hillis-Steele inclusive scan
    for (int d = 1; d < 1024; d <<= 1) {
        int v = (t >= d) ? sums[t - d] : 0;
        __syncthreads();
        sums[t] += v;
        __syncthreads();
    }
    int running = sums[t] - s;   // exclusive base for this chunk
    for (int i = lo; i < hi; i++) {
        g_off[i] = running;
        g_cur[i] = running;
        running += g_deg[i];
    }
    if (t == 1023) g_off[N_NODES] = sums[1023];
}

__global__ __launch_bounds__(256) void scatter_edges(
    const int* __restrict__ src, const int* __restrict__ dst)
{
    int e = blockIdx.x * blockDim.x + threadIdx.x;
    if (e >= N_EDGES) return;
    int pos = atomicAdd(&g_cur[dst[e]], 1);
    g_csr_src[pos] = src[e];
}

// ================= CSR aggregation: warp per node, no atomics =================
template<bool GATHER, bool EPI>
__global__ __launch_bounds__(256) void agg_csr(
    const int* __restrict__ cncpt, const float4* __restrict__ rows,
    const float* __restrict__ bias, float4* __restrict__ out)
{
    int w = (blockIdx.x * blockDim.x + threadIdx.x) >> 5;
    if (w >= N_NODES) return;
    int lane = threadIdx.x & 31;
    int beg = g_off[w], end = g_off[w + 1];

    float4 acc = make_float4(0.f, 0.f, 0.f, 0.f);
    int j = beg;
    for (; j + 4 <= end; j += 4) {
        int s0 = g_csr_src[j],     s1 = g_csr_src[j + 1];
        int s2 = g_csr_src[j + 2], s3 = g_csr_src[j + 3];
        if (GATHER) { s0 = cncpt[s0]; s1 = cncpt[s1]; s2 = cncpt[s2]; s3 = cncpt[s3]; }
        float4 v0 = rows[(size_t)s0 * 32 + lane];
        float4 v1 = rows[(size_t)s1 * 32 + lane];
        float4 v2 = rows[(size_t)s2 * 32 + lane];
        float4 v3 = rows[(size_t)s3 * 32 + lane];
        acc.x += v0.x; acc.y += v0.y; acc.z += v0.z; acc.w += v0.w;
        acc.x += v1.x; acc.y += v1.y; acc.z += v1.z; acc.w += v1.w;
        acc.x += v2.x; acc.y += v2.y; acc.z += v2.z; acc.w += v2.w;
        acc.x += v3.x; acc.y += v3.y; acc.z += v3.z; acc.w += v3.w;
    }
    for (; j < end; j++) {
        int s = g_csr_src[j];
        if (GATHER) s = cncpt[s];
        float4 v = rows[(size_t)s * 32 + lane];
        acc.x += v.x; acc.y += v.y; acc.z += v.z; acc.w += v.w;
    }
    if (EPI) {
        float4 b = ((const float4*)bias)[lane];
        acc.x = fmaxf(acc.x + b.x, 0.f);
        acc.y = fmaxf(acc.y + b.y, 0.f);
        acc.z = fmaxf(acc.z + b.z, 0.f);
        acc.w = fmaxf(acc.w + b.w, 0.f);
    }
    out[(size_t)w * 32 + lane] = acc;
}

// ================= SIMT fp32 GEMM with packed f32x2 FMA =================
// Accumulator pairs along M so the FFMA2 A-operand comes straight from the
// As float4 loads (no splat); only 4 B-splats per k-step.
template<int KDIM, int NDIM, bool EPI>
__global__ __launch_bounds__(256) void gemm_kernel(
    const float* __restrict__ A, const float* __restrict__ B,
    const float* __restrict__ bias, float* __restrict__ C, int M)
{
    constexpr int BM = 128, BN = 64, BK = 16;
    __shared__ float As[BK][BM + 4];   // transposed: As[k][m]
    __shared__ float Bs[BK][BN];

    const int tid = threadIdx.x;
    const int blockM = blockIdx.y * BM;
    const int blockN = blockIdx.x * BN;

    const int ty = tid >> 4;        // 0..15
    const int tx = tid & 15;        // 0..15
    const int tm0 = ty * 8;         // 8 rows (4 m-pairs)
    const int tn0 = tx * 4;         // 4 cols

    unsigned long long acc[4][4];   // [mpair][n], each is f32x2 over (m,m+1)
#pragma unroll
    for (int i = 0; i < 4; i++)
#pragma unroll
        for (int j = 0; j < 4; j++) acc[i][j] = 0ull;

    for (int k0 = 0; k0 < KDIM; k0 += BK) {
        // A tile (BM x BK) -> As[k][m] transposed
#pragma unroll
        for (int i = 0; i < 2; i++) {
            int f  = tid + i * 256;
            int m  = f >> 2;
            int kq = (f & 3) * 4;
            int gm = blockM + m;
            float4 v = make_float4(0.f, 0.f, 0.f, 0.f);
            if (gm < M)
                v = *(const float4*)(A + (size_t)gm * KDIM + k0 + kq);
            As[kq + 0][m] = v.x;
            As[kq + 1][m] = v.y;
            As[kq + 2][m] = v.z;
            As[kq + 3][m] = v.w;
        }
        // B tile (BK x BN)
        {
            int k  = tid >> 4;
            int nq = (tid & 15) * 4;
            *(float4*)&Bs[k][nq] =
                *(const float4*)(B + (size_t)(k0 + k) * NDIM + blockN + nq);
        }
        __syncthreads();

#pragma unroll
        for (int k = 0; k < BK; k++) {
            float4 a01 = *(const float4*)&As[k][tm0];      // m-pairs 0,1
            float4 a23 = *(const float4*)&As[k][tm0 + 4];  // m-pairs 2,3
            float4 b   = *(const float4*)&Bs[k][tn0];

            unsigned long long ap[4];
            memcpy(&ap[0], &a01.x, 8);
            memcpy(&ap[1], &a01.z, 8);
            memcpy(&ap[2], &a23.x, 8);
            memcpy(&ap[3], &a23.z, 8);

            unsigned long long bp[4];
            asm("mov.b64 %0, {%1, %1};" : "=l"(bp[0]) : "f"(b.x));
            asm("mov.b64 %0, {%1, %1};" : "=l"(bp[1]) : "f"(b.y));
            asm("mov.b64 %0, {%1, %1};" : "=l"(bp[2]) : "f"(b.z));
            asm("mov.b64 %0, {%1, %1};" : "=l"(bp[3]) : "f"(b.w));

#pragma unroll
            for (int i = 0; i < 4; i++) {
#pragma unroll
                for (int j = 0; j < 4; j++) {
                    asm("fma.rn.f32x2 %0, %1, %2, %3;"
                        : "=l"(acc[i][j]) : "l"(ap[i]), "l"(bp[j]), "l"(acc[i][j]));
                }
            }
        }
        __syncthreads();
    }

    float bs[4] = {0.f, 0.f, 0.f, 0.f};
    if (EPI) {
#pragma unroll
        for (int j = 0; j < 4; j++) bs[j] = bias[blockN + tn0 + j];
    }

#pragma unroll
    for (int i = 0; i < 4; i++) {
        float2 p[4];
#pragma unroll
        for (int j = 0; j < 4; j++) memcpy(&p[j], &acc[i][j], 8);

        int gm0 = blockM + tm0 + 2 * i;
#pragma unroll
        for (int r = 0; r < 2; r++) {
            int gm = gm0 + r;
            if (gm >= M) continue;
            float4 o;
            o.x = r ? p[0].y : p[0].x;
            o.y = r ? p[1].y : p[1].x;
            o.z = r ? p[2].y : p[2].x;
            o.w = r ? p[3].y : p[3].x;
            if (EPI) {
                o.x = fmaxf(o.x + bs[0], 0.f);
                o.y = fmaxf(o.y + bs[1], 0.f);
                o.z = fmaxf(o.z + bs[2], 0.f);
                o.w = fmaxf(o.w + bs[3], 0.f);
            }
            *(float4*)(C + (size_t)gm * NDIM + blockN + tn0) = o;
        }
    }
}

// ---------------- launch ----------------
extern "C" void kernel_launch(void* const* d_in, const int* in_sizes, int n_in,
                              void* d_out, int out_size) {
    const int*   cncpt = (const int*)d_in[0];
    const int*   src   = (const int*)d_in[1];
    const int*   dst   = (const int*)d_in[2];
    const float* emb   = (const float*)d_in[3];
    const float* W1    = (const float*)d_in[4];
    const float* b1    = (const float*)d_in[5];
    const float* W2    = (const float*)d_in[6];
    const float* b2    = (const float*)d_in[7];
    float* out = (float*)d_out;

    float *agg1, *h1, *t2;
    cudaGetSymbolAddress((void**)&agg1, g_agg1);
    cudaGetSymbolAddress((void**)&h1,  g_h1);
    cudaGetSymbolAddress((void**)&t2,  g_t2);

    // ---- build CSR (by dst) once; reused by both layers ----
    zero_deg<<<(N_NODES + 255) / 256, 256>>>();
    hist_dst<<<(N_EDGES + 255) / 256, 256>>>(dst);
    scan_deg<<<1, 1024>>>();
    scatter_edges<<<(N_EDGES + 255) / 256, 256>>>(src, dst);

    const int agg_blocks = (N_NODES * 32 + 255) / 256;

    // layer 1 aggregation: agg1[n] = sum_{e: dst=n} emb[cncpt[src[e]]]
    agg_csr<true, false><<<agg_blocks, 256>>>(cncpt, (const float4*)emb, nullptr, (float4*)agg1);

    // h1 = relu(agg1 @ W1 + b1)   [50000 x 256], K=128
    {
        dim3 grid(D_HID / 64, (N_NODES + 127) / 128);
        gemm_kernel<D_IN, D_HID, true><<<grid, 256>>>(agg1, W1, b1, h1, N_NODES);
    }

    // t2 = h1 @ W2   [50000 x 128], K=256   (GEMM commuted before aggregation)
    {
        dim3 grid(D_OUT / 64, (N_NODES + 127) / 128);
        gemm_kernel<D_HID, D_OUT, false><<<grid, 256>>>(h1, W2, nullptr, t2, N_NODES);
    }

    // layer 2 aggregation + bias + relu, straight into d_out
    agg_csr<false, true><<<agg_blocks, 256>>>(nullptr, (const float4*)t2, b2, (float4*)out);
}

// round 4
// speedup vs baseline: 1.3967x; 1.2407x over previous
#include <cuda_runtime.h>
#include <cuda_bf16.h>
#include <cstdint>

#define N_NODES 50000
#define N_EDGES 800000
#define D_IN 128
#define D_HID 256
#define D_OUT 128

// ---------------- scratch (static device arrays; no allocation) ----------------
__device__ float g_agg1[(size_t)N_NODES * D_IN];   // 25.6 MB
__device__ float g_h1[(size_t)N_NODES * D_HID];    // 51.2 MB
__device__ float g_t2[(size_t)N_NODES * D_OUT];    // 25.6 MB
__device__ float g_w1t[D_HID * D_IN];              // W1^T [256][128]
__device__ float g_w2t[D_OUT * D_HID];             // W2^T [128][256]
__device__ int   g_deg[N_NODES];
__device__ int   g_off[N_NODES + 1];
__device__ int   g_cur[N_NODES];
__device__ int   g_csr_src[N_EDGES];

// ================= small helpers =================
__device__ __forceinline__ uint32_t smem_u32(const void* p) {
    uint32_t a;
    asm("{ .reg .u64 t; cvta.to.shared.u64 t, %1; cvt.u32.u64 %0, t; }" : "=r"(a) : "l"(p));
    return a;
}

// split fp32 pair -> (hi bf16x2, lo bf16x2)
__device__ __forceinline__ void split2(float a0, float a1, uint32_t& hi, uint32_t& lo) {
    asm("cvt.rn.bf16x2.f32 %0, %1, %2;" : "=r"(hi) : "f"(a1), "f"(a0));
    float h0 = __uint_as_float(hi << 16);
    float h1 = __uint_as_float(hi & 0xFFFF0000u);
    float l0 = a0 - h0, l1 = a1 - h1;
    asm("cvt.rn.bf16x2.f32 %0, %1, %2;" : "=r"(lo) : "f"(l1), "f"(l0));
}

__device__ __forceinline__ void ldsm_x4(uint32_t* r, uint32_t addr) {
    asm volatile("ldmatrix.sync.aligned.m8n8.x4.shared.b16 {%0,%1,%2,%3}, [%4];"
                 : "=r"(r[0]), "=r"(r[1]), "=r"(r[2]), "=r"(r[3]) : "r"(addr));
}

__device__ __forceinline__ void mma16816(float* d, const uint32_t* a, const uint32_t* b) {
    asm volatile("mma.sync.aligned.m16n8k16.row.col.f32.bf16.bf16.f32 "
                 "{%0,%1,%2,%3}, {%4,%5,%6,%7}, {%8,%9}, {%0,%1,%2,%3};"
                 : "+f"(d[0]), "+f"(d[1]), "+f"(d[2]), "+f"(d[3])
                 : "r"(a[0]), "r"(a[1]), "r"(a[2]), "r"(a[3]), "r"(b[0]), "r"(b[1]));
}

// ================= CSR build =================
__global__ void zero_deg() {
    int i = blockIdx.x * blockDim.x + threadIdx.x;
    if (i < N_NODES) g_deg[i] = 0;
}
__global__ __launch_bounds__(256) void hist_dst(const int* __restrict__ dst) {
    int e = blockIdx.x * blockDim.x + threadIdx.x;
    if (e < N_EDGES) atomicAdd(&g_deg[dst[e]], 1);
}
__global__ __launch_bounds__(1024) void scan_deg() {
    __shared__ int sums[1024];
    const int CHUNK = (N_NODES + 1023) / 1024;
    int t = threadIdx.x;
    int lo = t * CHUNK;
    int hi = min(lo + CHUNK, N_NODES);
    int s = 0;
    for (int i = lo; i < hi; i++) s += g_deg[i];
    sums[t] = s;
    __syncthreads();
    for (int d = 1; d < 1024; d <<= 1) {
        int v = (t >= d) ? sums[t - d] : 0;
        __syncthreads();
        sums[t] += v;
        __syncthreads();
    }
    int running = sums[t] - s;
    for (int i = lo; i < hi; i++) {
        g_off[i] = running;
        g_cur[i] = running;
        running += g_deg[i];
    }
    if (t == 1023) g_off[N_NODES] = sums[1023];
}
__global__ __launch_bounds__(256) void scatter_edges(
    const int* __restrict__ src, const int* __restrict__ dst)
{
    int e = blockIdx.x * blockDim.x + threadIdx.x;
    if (e >= N_EDGES) return;
    int pos = atomicAdd(&g_cur[dst[e]], 1);
    g_csr_src[pos] = src[e];
}

// ================= CSR aggregation: warp per node, no atomics =================
template<bool GATHER, bool EPI>
__global__ __launch_bounds__(256) void agg_csr(
    const int* __restrict__ cncpt, const float4* __restrict__ rows,
    const float* __restrict__ bias, float4* __restrict__ out)
{
    int w = (blockIdx.x * blockDim.x + threadIdx.x) >> 5;
    if (w >= N_NODES) return;
    int lane = threadIdx.x & 31;
    int beg = g_off[w], end = g_off[w + 1];

    float4 acc = make_float4(0.f, 0.f, 0.f, 0.f);
    int j = beg;
    for (; j + 4 <= end; j += 4) {
        int s0 = g_csr_src[j],     s1 = g_csr_src[j + 1];
        int s2 = g_csr_src[j + 2], s3 = g_csr_src[j + 3];
        if (GATHER) { s0 = cncpt[s0]; s1 = cncpt[s1]; s2 = cncpt[s2]; s3 = cncpt[s3]; }
        float4 v0 = rows[(size_t)s0 * 32 + lane];
        float4 v1 = rows[(size_t)s1 * 32 + lane];
        float4 v2 = rows[(size_t)s2 * 32 + lane];
        float4 v3 = rows[(size_t)s3 * 32 + lane];
        acc.x += v0.x; acc.y += v0.y; acc.z += v0.z; acc.w += v0.w;
        acc.x += v1.x; acc.y += v1.y; acc.z += v1.z; acc.w += v1.w;
        acc.x += v2.x; acc.y += v2.y; acc.z += v2.z; acc.w += v2.w;
        acc.x += v3.x; acc.y += v3.y; acc.z += v3.z; acc.w += v3.w;
    }
    for (; j < end; j++) {
        int s = g_csr_src[j];
        if (GATHER) s = cncpt[s];
        float4 v = rows[(size_t)s * 32 + lane];
        acc.x += v.x; acc.y += v.y; acc.z += v.z; acc.w += v.w;
    }
    if (EPI) {
        float4 b = ((const float4*)bias)[lane];
        acc.x = fmaxf(acc.x + b.x, 0.f);
        acc.y = fmaxf(acc.y + b.y, 0.f);
        acc.z = fmaxf(acc.z + b.z, 0.f);
        acc.w = fmaxf(acc.w + b.w, 0.f);
    }
    out[(size_t)w * 32 + lane] = acc;
}

// ================= weight transpose (tiny) =================
__global__ void transpose_mat(const float* __restrict__ W, float* __restrict__ WT, int K, int N) {
    int i = blockIdx.x * blockDim.x + threadIdx.x;   // WT is [N][K]
    if (i >= N * K) return;
    int n = i / K, k = i % K;
    WT[i] = W[(size_t)k * N + n];
}

// ================= HMMA split-bf16 GEMM =================
// C[M,NN] = A[M,KK] @ BT[NN,KK]^T  via mma.sync m16n8k16 bf16, fp32 accumulate,
// 3-product split (Ah*Bh + Ah*Bl + Al*Bh). CTA tile 128x128, BK=32, 8 warps.
template<int NN, int KK, bool EPI>
__global__ __launch_bounds__(256) void hmma_gemm(
    const float* __restrict__ A, const float* __restrict__ BT,
    const float* __restrict__ bias, float* __restrict__ C, int M)
{
    constexpr int PAD = 40;   // b16 stride: 80 B -> conflict-free ldmatrix
    __shared__ __align__(16) __nv_bfloat16 As[2][128][PAD];   // [hi/lo][m][k]
    __shared__ __align__(16) __nv_bfloat16 Bs[2][128][PAD];   // [hi/lo][n][k]

    const int tid  = threadIdx.x;
    const int wid  = tid >> 5;
    const int lane = tid & 31;
    const int wm   = wid & 3;           // 0..3  -> m offset wm*32
    const int wn   = wid >> 2;          // 0..1  -> n offset wn*64
    const int blockM = blockIdx.y * 128;
    const int blockN = blockIdx.x * 128;

    const uint32_t as_base = smem_u32(&As[0][0][0]);
    const uint32_t bs_base = smem_u32(&Bs[0][0][0]);
    constexpr uint32_t PL = 128 * PAD * 2;   // plane size (hi->lo) in bytes

    // ldmatrix per-lane address components
    const int a_row = wm * 32 + (lane & 15);
    const int a_kof = (lane >> 4) << 3;
    const int b_row = wn * 64 + ((lane >> 4) << 3) + (lane & 7);
    const int b_kof = ((lane >> 3) & 1) << 3;

    float acc[2][8][4];
#pragma unroll
    for (int mt = 0; mt < 2; mt++)
#pragma unroll
        for (int j = 0; j < 8; j++)
#pragma unroll
            for (int q = 0; q < 4; q++) acc[mt][j][q] = 0.f;

    for (int kc = 0; kc < KK; kc += 32) {
        // ---- load A chunk: 128 x 32 fp32 -> hi/lo bf16 ----
#pragma unroll
        for (int i = 0; i < 4; i++) {
            int f  = tid + i * 256;          // 0..1023
            int r  = f >> 3;                 // 0..127
            int c4 = (f & 7) * 4;            // 0..28
            int gm = blockM + r;
            float4 v = make_float4(0.f, 0.f, 0.f, 0.f);
            if (gm < M) v = *(const float4*)(A + (size_t)gm * KK + kc + c4);
            uint32_t h0, l0, h1, l1;
            split2(v.x, v.y, h0, l0);
            split2(v.z, v.w, h1, l1);
            *(uint2*)&As[0][r][c4] = make_uint2(h0, h1);
            *(uint2*)&As[1][r][c4] = make_uint2(l0, l1);
        }
        // ---- load B chunk: 128 x 32 fp32 (rows of BT) ----
#pragma unroll
        for (int i = 0; i < 4; i++) {
            int f  = tid + i * 256;
            int r  = f >> 3;
            int c4 = (f & 7) * 4;
            float4 v = *(const float4*)(BT + (size_t)(blockN + r) * KK + kc + c4);
            uint32_t h0, l0, h1, l1;
            split2(v.x, v.y, h0, l0);
            split2(v.z, v.w, h1, l1);
            *(uint2*)&Bs[0][r][c4] = make_uint2(h0, h1);
            *(uint2*)&Bs[1][r][c4] = make_uint2(l0, l1);
        }
        __syncthreads();

#pragma unroll
        for (int kh = 0; kh < 2; kh++) {
            const int k16 = kh * 16;
            uint32_t ah[2][4], al[2][4], bh[8][2], bl[8][2];
#pragma unroll
            for (int mt = 0; mt < 2; mt++) {
                uint32_t off = ((a_row + mt * 16) * PAD + k16 + a_kof) * 2;
                ldsm_x4(ah[mt], as_base + off);
                ldsm_x4(al[mt], as_base + PL + off);
            }
#pragma unroll
            for (int jj = 0; jj < 4; jj++) {
                uint32_t off = ((b_row + jj * 16) * PAD + k16 + b_kof) * 2;
                uint32_t t[4];
                ldsm_x4(t, bs_base + off);
                bh[2 * jj][0] = t[0]; bh[2 * jj][1] = t[1];
                bh[2 * jj + 1][0] = t[2]; bh[2 * jj + 1][1] = t[3];
                ldsm_x4(t, bs_base + PL + off);
                bl[2 * jj][0] = t[0]; bl[2 * jj][1] = t[1];
                bl[2 * jj + 1][0] = t[2]; bl[2 * jj + 1][1] = t[3];
            }
            // three passes; each acc revisited only every 16 HMMA (no RAW stall)
#pragma unroll
            for (int mt = 0; mt < 2; mt++)
#pragma unroll
                for (int j = 0; j < 8; j++) mma16816(acc[mt][j], ah[mt], bh[j]);
#pragma unroll
            for (int mt = 0; mt < 2; mt++)
#pragma unroll
                for (int j = 0; j < 8; j++) mma16816(acc[mt][j], ah[mt], bl[j]);
#pragma unroll
            for (int mt = 0; mt < 2; mt++)
#pragma unroll
                for (int j = 0; j < 8; j++) mma16816(acc[mt][j], al[mt], bh[j]);
        }
        __syncthreads();
    }

    // ---- epilogue from C fragments (fused bias + relu) ----
    const int m_base = blockM + wm * 32 + (lane >> 2);
    const int n_base = blockN + wn * 64 + 2 * (lane & 3);
#pragma unroll
    for (int mt = 0; mt < 2; mt++) {
#pragma unroll
        for (int j = 0; j < 8; j++) {
            int n = n_base + 8 * j;
            float2 v0 = make_float2(acc[mt][j][0], acc[mt][j][1]);
            float2 v1 = make_float2(acc[mt][j][2], acc[mt][j][3]);
            if (EPI) {
                float bb0 = bias[n], bb1 = bias[n + 1];
                v0.x = fmaxf(v0.x + bb0, 0.f); v0.y = fmaxf(v0.y + bb1, 0.f);
                v1.x = fmaxf(v1.x + bb0, 0.f); v1.y = fmaxf(v1.y + bb1, 0.f);
            }
            int m = m_base + mt * 16;
            if (m < M)     *(float2*)(C + (size_t)m * NN + n)       = v0;
            if (m + 8 < M) *(float2*)(C + (size_t)(m + 8) * NN + n) = v1;
        }
    }
}

// ---------------- launch ----------------
extern "C" void kernel_launch(void* const* d_in, const int* in_sizes, int n_in,
                              void* d_out, int out_size) {
    const int*   cncpt = (const int*)d_in[0];
    const int*   src   = (const int*)d_in[1];
    const int*   dst   = (const int*)d_in[2];
    const float* emb   = (const float*)d_in[3];
    const float* W1    = (const float*)d_in[4];
    const float* b1    = (const float*)d_in[5];
    const float* W2    = (const float*)d_in[6];
    const float* b2    = (const float*)d_in[7];
    float* out = (float*)d_out;

    float *agg1, *h1, *t2, *w1t, *w2t;
    cudaGetSymbolAddress((void**)&agg1, g_agg1);
    cudaGetSymbolAddress((void**)&h1,   g_h1);
    cudaGetSymbolAddress((void**)&t2,   g_t2);
    cudaGetSymbolAddress((void**)&w1t,  g_w1t);
    cudaGetSymbolAddress((void**)&w2t,  g_w2t);

    // ---- build CSR (by dst) ----
    zero_deg<<<(N_NODES + 255) / 256, 256>>>();
    hist_dst<<<(N_EDGES + 255) / 256, 256>>>(dst);
    scan_deg<<<1, 1024>>>();
    scatter_edges<<<(N_EDGES + 255) / 256, 256>>>(src, dst);

    // ---- weight transposes (tiny) ----
    transpose_mat<<<(D_HID * D_IN + 255) / 256, 256>>>(W1, w1t, D_IN, D_HID);
    transpose_mat<<<(D_OUT * D_HID + 255) / 256, 256>>>(W2, w2t, D_HID, D_OUT);

    const int agg_blocks = (N_NODES * 32 + 255) / 256;
    const int mblocks = (N_NODES + 127) / 128;   // 391

    // layer 1 aggregation
    agg_csr<true, false><<<agg_blocks, 256>>>(cncpt, (const float4*)emb, nullptr, (float4*)agg1);

    // h1 = relu(agg1 @ W1 + b1)   [50000 x 256], K=128
    hmma_gemm<D_HID, D_IN, true><<<dim3(D_HID / 128, mblocks), 256>>>(agg1, w1t, b1, h1, N_NODES);

    // t2 = h1 @ W2   [50000 x 128], K=256  (GEMM commuted before aggregation)
    hmma_gemm<D_OUT, D_HID, false><<<dim3(D_OUT / 128, mblocks), 256>>>(h1, w2t, nullptr, t2, N_NODES);

    // layer 2 aggregation + bias + relu into d_out
    agg_csr<false, true><<<agg_blocks, 256>>>(nullptr, (const float4*)t2, b2, (float4*)out);
}

// round 5
// speedup vs baseline: 1.5149x; 1.0846x over previous
#include <cuda_runtime.h>
#include <cuda_bf16.h>
#include <cstdint>

#define N_NODES 50000
#define N_EDGES 800000
#define D_IN 128
#define D_HID 256
#define D_OUT 128

// ---------------- scratch (static device arrays; no allocation) ----------------
__device__ __nv_bfloat16 g_a1h[(size_t)N_NODES * D_IN];    // agg1 hi   12.8 MB
__device__ __nv_bfloat16 g_a1l[(size_t)N_NODES * D_IN];    // agg1 lo
__device__ __nv_bfloat16 g_h1h[(size_t)N_NODES * D_HID];   // h1 hi     25.6 MB
__device__ __nv_bfloat16 g_h1l[(size_t)N_NODES * D_HID];   // h1 lo
__device__ float         g_t2[(size_t)N_NODES * D_OUT];    // 25.6 MB
__device__ __nv_bfloat16 g_w1th[D_HID * D_IN], g_w1tl[D_HID * D_IN];
__device__ __nv_bfloat16 g_w2th[D_OUT * D_HID], g_w2tl[D_OUT * D_HID];
__device__ int g_deg[N_NODES];
__device__ int g_off[N_NODES + 1];
__device__ int g_cur[N_NODES];
__device__ int g_csr_src[N_EDGES];

// ================= small helpers =================
__device__ __forceinline__ uint32_t smem_u32(const void* p) {
    uint32_t a;
    asm("{ .reg .u64 t; cvta.to.shared.u64 t, %1; cvt.u32.u64 %0, t; }" : "=r"(a) : "l"(p));
    return a;
}

// split fp32 pair -> (hi bf16x2, lo bf16x2); low half of the b32 = first elem
__device__ __forceinline__ void split2(float a0, float a1, uint32_t& hi, uint32_t& lo) {
    asm("cvt.rn.bf16x2.f32 %0, %1, %2;" : "=r"(hi) : "f"(a1), "f"(a0));
    float h0 = __uint_as_float(hi << 16);
    float h1 = __uint_as_float(hi & 0xFFFF0000u);
    float l0 = a0 - h0, l1 = a1 - h1;
    asm("cvt.rn.bf16x2.f32 %0, %1, %2;" : "=r"(lo) : "f"(l1), "f"(l0));
}

__device__ __forceinline__ void ldsm_x4(uint32_t* r, uint32_t addr) {
    asm volatile("ldmatrix.sync.aligned.m8n8.x4.shared.b16 {%0,%1,%2,%3}, [%4];"
                 : "=r"(r[0]), "=r"(r[1]), "=r"(r[2]), "=r"(r[3]) : "r"(addr));
}

__device__ __forceinline__ void mma16816(float* d, const uint32_t* a, const uint32_t* b) {
    asm volatile("mma.sync.aligned.m16n8k16.row.col.f32.bf16.bf16.f32 "
                 "{%0,%1,%2,%3}, {%4,%5,%6,%7}, {%8,%9}, {%0,%1,%2,%3};"
                 : "+f"(d[0]), "+f"(d[1]), "+f"(d[2]), "+f"(d[3])
                 : "r"(a[0]), "r"(a[1]), "r"(a[2]), "r"(a[3]), "r"(b[0]), "r"(b[1]));
}

__device__ __forceinline__ void cp_async16(uint32_t dst, const void* src, int size) {
    asm volatile("cp.async.cg.shared.global [%0], [%1], 16, %2;"
                 :: "r"(dst), "l"(src), "r"(size) : "memory");
}

// ================= CSR build =================
__global__ void zero_deg() {
    int i = blockIdx.x * blockDim.x + threadIdx.x;
    if (i < N_NODES) g_deg[i] = 0;
}
__global__ __launch_bounds__(256) void hist_dst(const int* __restrict__ dst) {
    int e = blockIdx.x * blockDim.x + threadIdx.x;
    if (e < N_EDGES) atomicAdd(&g_deg[dst[e]], 1);
}
__global__ __launch_bounds__(1024) void scan_deg() {
    __shared__ int sums[1024];
    const int CHUNK = (N_NODES + 1023) / 1024;
    int t = threadIdx.x;
    int lo = t * CHUNK;
    int hi = min(lo + CHUNK, N_NODES);
    int s = 0;
    for (int i = lo; i < hi; i++) s += g_deg[i];
    sums[t] = s;
    __syncthreads();
    for (int d = 1; d < 1024; d <<= 1) {
        int v = (t >= d) ? sums[t - d] : 0;
        __syncthreads();
        sums[t] += v;
        __syncthreads();
    }
    int running = sums[t] - s;
    for (int i = lo; i < hi; i++) {
        g_off[i] = running;
        g_cur[i] = running;
        running += g_deg[i];
    }
    if (t == 1023) g_off[N_NODES] = sums[1023];
}
__global__ __launch_bounds__(256) void scatter_edges(
    const int* __restrict__ src, const int* __restrict__ dst)
{
    int e = blockIdx.x * blockDim.x + threadIdx.x;
    if (e >= N_EDGES) return;
    int pos = atomicAdd(&g_cur[dst[e]], 1);
    g_csr_src[pos] = src[e];
}

// ================= CSR aggregation: warp per node, no atomics =================
// SPLIT: write hi/lo bf16 planes (feeds the bf16 GEMM). else: fp32 (+bias+relu).
template<bool GATHER, bool EPI, bool SPLIT>
__global__ __launch_bounds__(256) void agg_csr(
    const int* __restrict__ cncpt, const float4* __restrict__ rows,
    const float* __restrict__ bias, float4* __restrict__ outf,
    __nv_bfloat16* __restrict__ oh, __nv_bfloat16* __restrict__ ol)
{
    int w = (blockIdx.x * blockDim.x + threadIdx.x) >> 5;
    if (w >= N_NODES) return;
    int lane = threadIdx.x & 31;
    int beg = g_off[w], end = g_off[w + 1];

    float4 acc = make_float4(0.f, 0.f, 0.f, 0.f);
    int j = beg;
    for (; j + 4 <= end; j += 4) {
        int s0 = g_csr_src[j],     s1 = g_csr_src[j + 1];
        int s2 = g_csr_src[j + 2], s3 = g_csr_src[j + 3];
        if (GATHER) { s0 = cncpt[s0]; s1 = cncpt[s1]; s2 = cncpt[s2]; s3 = cncpt[s3]; }
        float4 v0 = rows[(size_t)s0 * 32 + lane];
        float4 v1 = rows[(size_t)s1 * 32 + lane];
        float4 v2 = rows[(size_t)s2 * 32 + lane];
        float4 v3 = rows[(size_t)s3 * 32 + lane];
        acc.x += v0.x; acc.y += v0.y; acc.z += v0.z; acc.w += v0.w;
        acc.x += v1.x; acc.y += v1.y; acc.z += v1.z; acc.w += v1.w;
        acc.x += v2.x; acc.y += v2.y; acc.z += v2.z; acc.w += v2.w;
        acc.x += v3.x; acc.y += v3.y; acc.z += v3.z; acc.w += v3.w;
    }
    for (; j < end; j++) {
        int s = g_csr_src[j];
        if (GATHER) s = cncpt[s];
        float4 v = rows[(size_t)s * 32 + lane];
        acc.x += v.x; acc.y += v.y; acc.z += v.z; acc.w += v.w;
    }
    if (EPI) {
        float4 b = ((const float4*)bias)[lane];
        acc.x = fmaxf(acc.x + b.x, 0.f);
        acc.y = fmaxf(acc.y + b.y, 0.f);
        acc.z = fmaxf(acc.z + b.z, 0.f);
        acc.w = fmaxf(acc.w + b.w, 0.f);
    }
    if (SPLIT) {
        uint32_t h0, l0, h1, l1;
        split2(acc.x, acc.y, h0, l0);
        split2(acc.z, acc.w, h1, l1);
        size_t off = (size_t)w * 128 + lane * 4;
        *(uint2*)(oh + off) = make_uint2(h0, h1);
        *(uint2*)(ol + off) = make_uint2(l0, l1);
    } else {
        outf[(size_t)w * 32 + lane] = acc;
    }
}

// ================= weight transpose + split (tiny) =================
__global__ void transpose_split(const float* __restrict__ W,
                                __nv_bfloat16* __restrict__ Th,
                                __nv_bfloat16* __restrict__ Tl, int K, int N) {
    int i = blockIdx.x * blockDim.x + threadIdx.x;   // T is [N][K]
    if (i >= N * K) return;
    int n = i / K, k = i % K;
    float v = W[(size_t)k * N + n];
    __nv_bfloat16 h = __float2bfloat16_rn(v);
    Th[i] = h;
    Tl[i] = __float2bfloat16_rn(v - __bfloat162float(h));
}

// ================= HMMA split-bf16 GEMM, cp.async double-buffered =================
// C[M,NN] = (Ah+Al)[M,KK] @ (Bh+Bl)[NN,KK]^T via 3 products, fp32 accumulate.
// CTA tile 128x128, BK=32, 8 warps, 2-stage cp.async pipeline.
// MODE 0: fp32 out. MODE 1: bias+relu then split bf16 out (hi/lo planes).
template<int NN, int KK, int MODE>
__global__ __launch_bounds__(256) void hmma_gemm(
    const __nv_bfloat16* __restrict__ Ah, const __nv_bfloat16* __restrict__ Al,
    const __nv_bfloat16* __restrict__ Bh, const __nv_bfloat16* __restrict__ Bl,
    const float* __restrict__ bias, float* __restrict__ Cf,
    __nv_bfloat16* __restrict__ Ch, __nv_bfloat16* __restrict__ Cl, int M)
{
    constexpr int PAD   = 40;               // bf16 row stride (80 B): ldmatrix conflict-free
    constexpr int PLANE = 128 * PAD;        // elements per plane
    constexpr int STAGE = 4 * PLANE;        // Ah | Al | Bh | Bl
    extern __shared__ __nv_bfloat16 smem[]; // [2][STAGE]

    const int tid  = threadIdx.x;
    const int wid  = tid >> 5;
    const int lane = tid & 31;
    const int wm   = wid & 3;
    const int wn   = wid >> 2;
    const int blockM = blockIdx.y * 128;
    const int blockN = blockIdx.x * 128;

    const uint32_t sb0 = smem_u32(smem);

    // ldmatrix per-lane address components
    const int a_row = wm * 32 + (lane & 15);
    const int a_kof = (lane >> 4) << 3;
    const int b_row = wn * 64 + ((lane >> 4) << 3) + (lane & 7);
    const int b_kof = ((lane >> 3) & 1) << 3;

    float acc[2][8][4];
#pragma unroll
    for (int mt = 0; mt < 2; mt++)
#pragma unroll
        for (int j = 0; j < 8; j++)
#pragma unroll
            for (int q = 0; q < 4; q++) acc[mt][j][q] = 0.f;

    // ---- stage loader: 2048 x 16B cp.async (8 per thread) ----
    auto load_stage = [&](int s, int kc) {
        uint32_t sb = sb0 + (uint32_t)s * STAGE * 2;
#pragma unroll
        for (int i = 0; i < 8; i++) {
            int g   = i * 256 + tid;          // 0..2047
            int p   = g >> 9;                 // plane 0..3
            int idx = g & 511;
            int row = idx >> 2;
            int k8  = (idx & 3) * 8;
            const __nv_bfloat16* src;
            int size = 16;
            if (p < 2) {
                int gm = blockM + row;
                int cm = gm < M ? gm : 0;
                if (gm >= M) size = 0;
                src = (p == 0 ? Ah : Al) + (size_t)cm * KK + kc + k8;
            } else {
                src = (p == 2 ? Bh : Bl) + (size_t)(blockN + row) * KK + kc + k8;
            }
            cp_async16(sb + (uint32_t)(p * PLANE + row * PAD + k8) * 2, src, size);
        }
        asm volatile("cp.async.commit_group;" ::: "memory");
    };

    constexpr int NC = KK / 32;
    load_stage(0, 0);

    for (int c = 0; c < NC; c++) {
        if (c + 1 < NC) {
            load_stage((c + 1) & 1, (c + 1) * 32);
            asm volatile("cp.async.wait_group 1;" ::: "memory");
        } else {
            asm volatile("cp.async.wait_group 0;" ::: "memory");
        }
        __syncthreads();

        const uint32_t base = sb0 + (uint32_t)(c & 1) * STAGE * 2;
#pragma unroll
        for (int kh = 0; kh < 2; kh++) {
            const int k16 = kh * 16;
            uint32_t ah[2][4], al[2][4], bh[8][2], bl[8][2];
#pragma unroll
            for (int mt = 0; mt < 2; mt++) {
                uint32_t off = ((a_row + mt * 16) * PAD + k16 + a_kof) * 2;
                ldsm_x4(ah[mt], base + off);
                ldsm_x4(al[mt], base + PLANE * 2 + off);
            }
#pragma unroll
            for (int jj = 0; jj < 4; jj++) {
                uint32_t off = ((b_row + jj * 16) * PAD + k16 + b_kof) * 2;
                uint32_t t[4];
                ldsm_x4(t, base + 2 * PLANE * 2 + off);
                bh[2 * jj][0] = t[0]; bh[2 * jj][1] = t[1];
                bh[2 * jj + 1][0] = t[2]; bh[2 * jj + 1][1] = t[3];
                ldsm_x4(t, base + 3 * PLANE * 2 + off);
                bl[2 * jj][0] = t[0]; bl[2 * jj][1] = t[1];
                bl[2 * jj + 1][0] = t[2]; bl[2 * jj + 1][1] = t[3];
            }
#pragma unroll
            for (int mt = 0; mt < 2; mt++)
#pragma unroll
                for (int j = 0; j < 8; j++) mma16816(acc[mt][j], ah[mt], bh[j]);
#pragma unroll
            for (int mt = 0; mt < 2; mt++)
#pragma unroll
                for (int j = 0; j < 8; j++) mma16816(acc[mt][j], ah[mt], bl[j]);
#pragma unroll
            for (int mt = 0; mt < 2; mt++)
#pragma unroll
                for (int j = 0; j < 8; j++) mma16816(acc[mt][j], al[mt], bh[j]);
        }
        __syncthreads();
    }

    // ---- epilogue from C fragments ----
    const int m_base = blockM + wm * 32 + (lane >> 2);
    const int n_base = blockN + wn * 64 + 2 * (lane & 3);
#pragma unroll
    for (int mt = 0; mt < 2; mt++) {
#pragma unroll
        for (int j = 0; j < 8; j++) {
            int n = n_base + 8 * j;
            float2 v0 = make_float2(acc[mt][j][0], acc[mt][j][1]);
            float2 v1 = make_float2(acc[mt][j][2], acc[mt][j][3]);
            int m = m_base + mt * 16;
            if (MODE == 1) {
                float bb0 = bias[n], bb1 = bias[n + 1];
                v0.x = fmaxf(v0.x + bb0, 0.f); v0.y = fmaxf(v0.y + bb1, 0.f);
                v1.x = fmaxf(v1.x + bb0, 0.f); v1.y = fmaxf(v1.y + bb1, 0.f);
                uint32_t h, l;
                if (m < M) {
                    split2(v0.x, v0.y, h, l);
                    *(uint32_t*)(Ch + (size_t)m * NN + n) = h;
                    *(uint32_t*)(Cl + (size_t)m * NN + n) = l;
                }
                if (m + 8 < M) {
                    split2(v1.x, v1.y, h, l);
                    *(uint32_t*)(Ch + (size_t)(m + 8) * NN + n) = h;
                    *(uint32_t*)(Cl + (size_t)(m + 8) * NN + n) = l;
                }
            } else {
                if (m < M)     *(float2*)(Cf + (size_t)m * NN + n)       = v0;
                if (m + 8 < M) *(float2*)(Cf + (size_t)(m + 8) * NN + n) = v1;
            }
        }
    }
}

// ---------------- launch ----------------
extern "C" void kernel_launch(void* const* d_in, const int* in_sizes, int n_in,
                              void* d_out, int out_size) {
    const int*   cncpt = (const int*)d_in[0];
    const int*   src   = (const int*)d_in[1];
    const int*   dst   = (const int*)d_in[2];
    const float* emb   = (const float*)d_in[3];
    const float* W1    = (const float*)d_in[4];
    const float* b1    = (const float*)d_in[5];
    const float* W2    = (const float*)d_in[6];
    const float* b2    = (const float*)d_in[7];
    float* out = (float*)d_out;

    __nv_bfloat16 *a1h, *a1l, *h1h, *h1l, *w1th, *w1tl, *w2th, *w2tl;
    float *t2;
    cudaGetSymbolAddress((void**)&a1h,  g_a1h);
    cudaGetSymbolAddress((void**)&a1l,  g_a1l);
    cudaGetSymbolAddress((void**)&h1h,  g_h1h);
    cudaGetSymbolAddress((void**)&h1l,  g_h1l);
    cudaGetSymbolAddress((void**)&t2,   g_t2);
    cudaGetSymbolAddress((void**)&w1th, g_w1th);
    cudaGetSymbolAddress((void**)&w1tl, g_w1tl);
    cudaGetSymbolAddress((void**)&w2th, g_w2th);
    cudaGetSymbolAddress((void**)&w2tl, g_w2tl);

    const int SMEM = 2 * 4 * 128 * 40 * 2;   // 81920 B
    cudaFuncSetAttribute(hmma_gemm<D_HID, D_IN, 1>,
                         cudaFuncAttributeMaxDynamicSharedMemorySize, SMEM);
    cudaFuncSetAttribute(hmma_gemm<D_OUT, D_HID, 0>,
                         cudaFuncAttributeMaxDynamicSharedMemorySize, SMEM);

    // ---- build CSR (by dst) ----
    zero_deg<<<(N_NODES + 255) / 256, 256>>>();
    hist_dst<<<(N_EDGES + 255) / 256, 256>>>(dst);
    scan_deg<<<1, 1024>>>();
    scatter_edges<<<(N_EDGES + 255) / 256, 256>>>(src, dst);

    // ---- weight transpose + pre-split (tiny) ----
    transpose_split<<<(D_HID * D_IN + 255) / 256, 256>>>(W1, w1th, w1tl, D_IN, D_HID);
    transpose_split<<<(D_OUT * D_HID + 255) / 256, 256>>>(W2, w2th, w2tl, D_HID, D_OUT);

    const int agg_blocks = (N_NODES * 32 + 255) / 256;
    const int mblocks = (N_NODES + 127) / 128;   // 391

    // layer 1 aggregation -> split bf16 planes
    agg_csr<true, false, true><<<agg_blocks, 256>>>(
        cncpt, (const float4*)emb, nullptr, nullptr, a1h, a1l);

    // h1 = relu(agg1 @ W1 + b1) -> split bf16 planes
    hmma_gemm<D_HID, D_IN, 1><<<dim3(D_HID / 128, mblocks), 256, SMEM>>>(
        a1h, a1l, w1th, w1tl, b1, nullptr, h1h, h1l, N_NODES);

    // t2 = h1 @ W2 (GEMM commuted before aggregation) -> fp32
    hmma_gemm<D_OUT, D_HID, 0><<<dim3(D_OUT / 128, mblocks), 256, SMEM>>>(
        h1h, h1l, w2th, w2tl, nullptr, t2, nullptr, nullptr, N_NODES);

    // layer 2 aggregation + bias + relu into d_out
    agg_csr<false, true, false><<<agg_blocks, 256>>>(
        nullptr, (const float4*)t2, b2, (float4*)out, nullptr, nullptr);
}

// round 6
// speedup vs baseline: 1.6136x; 1.0651x over previous
#include <cuda_runtime.h>
#include <cuda_bf16.h>
#include <cstdint>

#define N_NODES 50000
#define N_EDGES 800000
#define D_IN 128
#define D_HID 256
#define D_OUT 128

// ---------------- scratch (static device arrays; no allocation) ----------------
__device__ __nv_bfloat16 g_a1h[(size_t)N_NODES * D_IN];    // agg1 hi   12.8 MB
__device__ __nv_bfloat16 g_a1l[(size_t)N_NODES * D_IN];    // agg1 lo
__device__ __nv_bfloat16 g_h1h[(size_t)N_NODES * D_HID];   // h1 hi     25.6 MB
__device__ __nv_bfloat16 g_h1l[(size_t)N_NODES * D_HID];   // h1 lo
__device__ float         g_t2[(size_t)N_NODES * D_OUT];    // 25.6 MB
__device__ __nv_bfloat16 g_w1th[D_HID * D_IN], g_w1tl[D_HID * D_IN];
__device__ __nv_bfloat16 g_w2th[D_OUT * D_HID], g_w2tl[D_OUT * D_HID];
__device__ int g_deg[N_NODES];
__device__ int g_off[N_NODES + 1];
__device__ int g_cur[N_NODES];
__device__ int g_csr_src[N_EDGES];

// ================= small helpers =================
__device__ __forceinline__ uint32_t smem_u32(const void* p) {
    uint32_t a;
    asm("{ .reg .u64 t; cvta.to.shared.u64 t, %1; cvt.u32.u64 %0, t; }" : "=r"(a) : "l"(p));
    return a;
}

// split fp32 pair -> (hi bf16x2, lo bf16x2); low half of the b32 = first elem
__device__ __forceinline__ void split2(float a0, float a1, uint32_t& hi, uint32_t& lo) {
    asm("cvt.rn.bf16x2.f32 %0, %1, %2;" : "=r"(hi) : "f"(a1), "f"(a0));
    float h0 = __uint_as_float(hi << 16);
    float h1 = __uint_as_float(hi & 0xFFFF0000u);
    float l0 = a0 - h0, l1 = a1 - h1;
    asm("cvt.rn.bf16x2.f32 %0, %1, %2;" : "=r"(lo) : "f"(l1), "f"(l0));
}

__device__ __forceinline__ void ldsm_x4(uint32_t* r, uint32_t addr) {
    asm volatile("ldmatrix.sync.aligned.m8n8.x4.shared.b16 {%0,%1,%2,%3}, [%4];"
                 : "=r"(r[0]), "=r"(r[1]), "=r"(r[2]), "=r"(r[3]) : "r"(addr));
}

__device__ __forceinline__ void mma16816(float* d, const uint32_t* a, const uint32_t* b) {
    asm volatile("mma.sync.aligned.m16n8k16.row.col.f32.bf16.bf16.f32 "
                 "{%0,%1,%2,%3}, {%4,%5,%6,%7}, {%8,%9}, {%0,%1,%2,%3};"
                 : "+f"(d[0]), "+f"(d[1]), "+f"(d[2]), "+f"(d[3])
                 : "r"(a[0]), "r"(a[1]), "r"(a[2]), "r"(a[3]), "r"(b[0]), "r"(b[1]));
}

__device__ __forceinline__ void cp_async16(uint32_t dst, const void* src, int size) {
    asm volatile("cp.async.cg.shared.global [%0], [%1], 16, %2;"
                 :: "r"(dst), "l"(src), "r"(size) : "memory");
}

// swizzled smem byte offset within a plane: row stride 64B, chunk16 XOR (row>>1)&3
__device__ __forceinline__ uint32_t swz(int row, int chunk) {
    return (uint32_t)(row * 64 + ((chunk ^ ((row >> 1) & 3)) << 4));
}

// ================= CSR build =================
__global__ void zero_deg() {
    int i = blockIdx.x * blockDim.x + threadIdx.x;
    if (i < N_NODES) g_deg[i] = 0;
}
__global__ __launch_bounds__(256) void hist_dst(const int* __restrict__ dst) {
    int e = blockIdx.x * blockDim.x + threadIdx.x;
    if (e < N_EDGES) atomicAdd(&g_deg[dst[e]], 1);
}
__global__ __launch_bounds__(1024) void scan_deg() {
    __shared__ int sums[1024];
    const int CHUNK = (N_NODES + 1023) / 1024;
    int t = threadIdx.x;
    int lo = t * CHUNK;
    int hi = min(lo + CHUNK, N_NODES);
    int s = 0;
    for (int i = lo; i < hi; i++) s += g_deg[i];
    sums[t] = s;
    __syncthreads();
    for (int d = 1; d < 1024; d <<= 1) {
        int v = (t >= d) ? sums[t - d] : 0;
        __syncthreads();
        sums[t] += v;
        __syncthreads();
    }
    int running = sums[t] - s;
    for (int i = lo; i < hi; i++) {
        g_off[i] = running;
        g_cur[i] = running;
        running += g_deg[i];
    }
    if (t == 1023) g_off[N_NODES] = sums[1023];
}
__global__ __launch_bounds__(256) void scatter_edges(
    const int* __restrict__ src, const int* __restrict__ dst)
{
    int e = blockIdx.x * blockDim.x + threadIdx.x;
    if (e >= N_EDGES) return;
    int pos = atomicAdd(&g_cur[dst[e]], 1);
    g_csr_src[pos] = src[e];
}

// ================= CSR aggregation: warp per node, no atomics =================
template<bool GATHER, bool EPI, bool SPLIT>
__global__ __launch_bounds__(256) void agg_csr(
    const int* __restrict__ cncpt, const float4* __restrict__ rows,
    const float* __restrict__ bias, float4* __restrict__ outf,
    __nv_bfloat16* __restrict__ oh, __nv_bfloat16* __restrict__ ol)
{
    int w = (blockIdx.x * blockDim.x + threadIdx.x) >> 5;
    if (w >= N_NODES) return;
    int lane = threadIdx.x & 31;
    int beg = g_off[w], end = g_off[w + 1];

    float4 acc = make_float4(0.f, 0.f, 0.f, 0.f);
    int j = beg;
    for (; j + 4 <= end; j += 4) {
        int s0 = g_csr_src[j],     s1 = g_csr_src[j + 1];
        int s2 = g_csr_src[j + 2], s3 = g_csr_src[j + 3];
        if (GATHER) { s0 = cncpt[s0]; s1 = cncpt[s1]; s2 = cncpt[s2]; s3 = cncpt[s3]; }
        float4 v0 = rows[(size_t)s0 * 32 + lane];
        float4 v1 = rows[(size_t)s1 * 32 + lane];
        float4 v2 = rows[(size_t)s2 * 32 + lane];
        float4 v3 = rows[(size_t)s3 * 32 + lane];
        acc.x += v0.x; acc.y += v0.y; acc.z += v0.z; acc.w += v0.w;
        acc.x += v1.x; acc.y += v1.y; acc.z += v1.z; acc.w += v1.w;
        acc.x += v2.x; acc.y += v2.y; acc.z += v2.z; acc.w += v2.w;
        acc.x += v3.x; acc.y += v3.y; acc.z += v3.z; acc.w += v3.w;
    }
    for (; j < end; j++) {
        int s = g_csr_src[j];
        if (GATHER) s = cncpt[s];
        float4 v = rows[(size_t)s * 32 + lane];
        acc.x += v.x; acc.y += v.y; acc.z += v.z; acc.w += v.w;
    }
    if (EPI) {
        float4 b = ((const float4*)bias)[lane];
        acc.x = fmaxf(acc.x + b.x, 0.f);
        acc.y = fmaxf(acc.y + b.y, 0.f);
        acc.z = fmaxf(acc.z + b.z, 0.f);
        acc.w = fmaxf(acc.w + b.w, 0.f);
    }
    if (SPLIT) {
        uint32_t h0, l0, h1, l1;
        split2(acc.x, acc.y, h0, l0);
        split2(acc.z, acc.w, h1, l1);
        size_t off = (size_t)w * 128 + lane * 4;
        *(uint2*)(oh + off) = make_uint2(h0, h1);
        *(uint2*)(ol + off) = make_uint2(l0, l1);
    } else {
        outf[(size_t)w * 32 + lane] = acc;
    }
}

// ================= weight transpose + split (tiny) =================
__global__ void transpose_split(const float* __restrict__ W,
                                __nv_bfloat16* __restrict__ Th,
                                __nv_bfloat16* __restrict__ Tl, int K, int N) {
    int i = blockIdx.x * blockDim.x + threadIdx.x;   // T is [N][K]
    if (i >= N * K) return;
    int n = i / K, k = i % K;
    float v = W[(size_t)k * N + n];
    __nv_bfloat16 h = __float2bfloat16_rn(v);
    Th[i] = h;
    Tl[i] = __float2bfloat16_rn(v - __bfloat162float(h));
}

// ================= HMMA split-bf16 GEMM, cp.async double-buffered =================
// C[M,NN] = (Ah+Al)[M,KK] @ (Bh+Bl)[NN,KK]^T via 3 products, fp32 accumulate.
// CTA tile 128x128, BK=32, 8 warps, 2-stage pipeline, swizzled 64B-stride smem
// (32KB/stage, 64KB total) + __launch_bounds__(256,2) -> 2 CTAs/SM.
// MODE 0: fp32 out. MODE 1: bias+relu then split bf16 out (hi/lo planes).
template<int NN, int KK, int MODE>
__global__ __launch_bounds__(256, 2) void hmma_gemm(
    const __nv_bfloat16* __restrict__ Ah, const __nv_bfloat16* __restrict__ Al,
    const __nv_bfloat16* __restrict__ Bh, const __nv_bfloat16* __restrict__ Bl,
    const float* __restrict__ bias, float* __restrict__ Cf,
    __nv_bfloat16* __restrict__ Ch, __nv_bfloat16* __restrict__ Cl, int M)
{
    constexpr int PLANE_B = 128 * 64;        // plane bytes (128 rows x 64B)
    constexpr int STAGE_B = 4 * PLANE_B;     // Ah | Al | Bh | Bl = 32KB
    extern __shared__ __align__(16) char smem[];   // [2][STAGE_B]

    const int tid  = threadIdx.x;
    const int wid  = tid >> 5;
    const int lane = tid & 31;
    const int wm   = wid & 3;
    const int wn   = wid >> 2;
    const int blockM = blockIdx.y * 128;
    const int blockN = blockIdx.x * 128;

    const uint32_t sb0 = smem_u32(smem);

    // ldmatrix per-lane row / chunk components
    const int a_row = wm * 32 + (lane & 15);
    const int a_chk = lane >> 4;                               // 0..1
    const int b_row = wn * 64 + ((lane >> 4) << 3) + (lane & 7);
    const int b_chk = (lane >> 3) & 1;                         // 0..1

    float acc[2][8][4];
#pragma unroll
    for (int mt = 0; mt < 2; mt++)
#pragma unroll
        for (int j = 0; j < 8; j++)
#pragma unroll
            for (int q = 0; q < 4; q++) acc[mt][j][q] = 0.f;

    // ---- stage loader: 2048 x 16B cp.async (8 per thread), swizzled ----
    auto load_stage = [&](int s, int kc) {
        uint32_t sb = sb0 + (uint32_t)s * STAGE_B;
#pragma unroll
        for (int i = 0; i < 8; i++) {
            int g   = i * 256 + tid;          // 0..2047
            int p   = g >> 9;                 // plane 0..3
            int idx = g & 511;
            int row = idx >> 2;
            int c   = idx & 3;                // 16B chunk within row
            const __nv_bfloat16* src;
            int size = 16;
            if (p < 2) {
                int gm = blockM + row;
                int cm = gm < M ? gm : 0;
                if (gm >= M) size = 0;
                src = (p == 0 ? Ah : Al) + (size_t)cm * KK + kc + c * 8;
            } else {
                src = (p == 2 ? Bh : Bl) + (size_t)(blockN + row) * KK + kc + c * 8;
            }
            cp_async16(sb + (uint32_t)p * PLANE_B + swz(row, c), src, size);
        }
        asm volatile("cp.async.commit_group;" ::: "memory");
    };

    constexpr int NC = KK / 32;
    load_stage(0, 0);

    for (int c = 0; c < NC; c++) {
        if (c + 1 < NC) {
            load_stage((c + 1) & 1, (c + 1) * 32);
            asm volatile("cp.async.wait_group 1;" ::: "memory");
        } else {
            asm volatile("cp.async.wait_group 0;" ::: "memory");
        }
        __syncthreads();

        const uint32_t base = sb0 + (uint32_t)(c & 1) * STAGE_B;
#pragma unroll
        for (int kh = 0; kh < 2; kh++) {
            uint32_t ah[2][4], al[2][4], bh[8][2], bl[8][2];
#pragma unroll
            for (int mt = 0; mt < 2; mt++) {
                uint32_t off = swz(a_row + mt * 16, kh * 2 + a_chk);
                ldsm_x4(ah[mt], base + off);
                ldsm_x4(al[mt], base + PLANE_B + off);
            }
#pragma unroll
            for (int jj = 0; jj < 4; jj++) {
                uint32_t off = swz(b_row + jj * 16, kh * 2 + b_chk);
                uint32_t t[4];
                ldsm_x4(t, base + 2 * PLANE_B + off);
                bh[2 * jj][0] = t[0]; bh[2 * jj][1] = t[1];
                bh[2 * jj + 1][0] = t[2]; bh[2 * jj + 1][1] = t[3];
                ldsm_x4(t, base + 3 * PLANE_B + off);
                bl[2 * jj][0] = t[0]; bl[2 * jj][1] = t[1];
                bl[2 * jj + 1][0] = t[2]; bl[2 * jj + 1][1] = t[3];
            }
#pragma unroll
            for (int mt = 0; mt < 2; mt++)
#pragma unroll
                for (int j = 0; j < 8; j++) mma16816(acc[mt][j], ah[mt], bh[j]);
#pragma unroll
            for (int mt = 0; mt < 2; mt++)
#pragma unroll
                for (int j = 0; j < 8; j++) mma16816(acc[mt][j], ah[mt], bl[j]);
#pragma unroll
            for (int mt = 0; mt < 2; mt++)
#pragma unroll
                for (int j = 0; j < 8; j++) mma16816(acc[mt][j], al[mt], bh[j]);
        }
        __syncthreads();
    }

    // ---- epilogue from C fragments ----
    const int m_base = blockM + wm * 32 + (lane >> 2);
    const int n_base = blockN + wn * 64 + 2 * (lane & 3);
#pragma unroll
    for (int mt = 0; mt < 2; mt++) {
#pragma unroll
        for (int j = 0; j < 8; j++) {
            int n = n_base + 8 * j;
            float2 v0 = make_float2(acc[mt][j][0], acc[mt][j][1]);
            float2 v1 = make_float2(acc[mt][j][2], acc[mt][j][3]);
            int m = m_base + mt * 16;
            if (MODE == 1) {
                float bb0 = bias[n], bb1 = bias[n + 1];
                v0.x = fmaxf(v0.x + bb0, 0.f); v0.y = fmaxf(v0.y + bb1, 0.f);
                v1.x = fmaxf(v1.x + bb0, 0.f); v1.y = fmaxf(v1.y + bb1, 0.f);
                uint32_t h, l;
                if (m < M) {
                    split2(v0.x, v0.y, h, l);
                    *(uint32_t*)(Ch + (size_t)m * NN + n) = h;
                    *(uint32_t*)(Cl + (size_t)m * NN + n) = l;
                }
                if (m + 8 < M) {
                    split2(v1.x, v1.y, h, l);
                    *(uint32_t*)(Ch + (size_t)(m + 8) * NN + n) = h;
                    *(uint32_t*)(Cl + (size_t)(m + 8) * NN + n) = l;
                }
            } else {
                if (m < M)     *(float2*)(Cf + (size_t)m * NN + n)       = v0;
                if (m + 8 < M) *(float2*)(Cf + (size_t)(m + 8) * NN + n) = v1;
            }
        }
    }
}

// ---------------- launch ----------------
extern "C" void kernel_launch(void* const* d_in, const int* in_sizes, int n_in,
                              void* d_out, int out_size) {
    const int*   cncpt = (const int*)d_in[0];
    const int*   src   = (const int*)d_in[1];
    const int*   dst   = (const int*)d_in[2];
    const float* emb   = (const float*)d_in[3];
    const float* W1    = (const float*)d_in[4];
    const float* b1    = (const float*)d_in[5];
    const float* W2    = (const float*)d_in[6];
    const float* b2    = (const float*)d_in[7];
    float* out = (float*)d_out;

    __nv_bfloat16 *a1h, *a1l, *h1h, *h1l, *w1th, *w1tl, *w2th, *w2tl;
    float *t2;
    cudaGetSymbolAddress((void**)&a1h,  g_a1h);
    cudaGetSymbolAddress((void**)&a1l,  g_a1l);
    cudaGetSymbolAddress((void**)&h1h,  g_h1h);
    cudaGetSymbolAddress((void**)&h1l,  g_h1l);
    cudaGetSymbolAddress((void**)&t2,   g_t2);
    cudaGetSymbolAddress((void**)&w1th, g_w1th);
    cudaGetSymbolAddress((void**)&w1tl, g_w1tl);
    cudaGetSymbolAddress((void**)&w2th, g_w2th);
    cudaGetSymbolAddress((void**)&w2tl, g_w2tl);

    const int SMEM = 2 * 4 * 128 * 64;   // 65536 B
    cudaFuncSetAttribute(hmma_gemm<D_HID, D_IN, 1>,
                         cudaFuncAttributeMaxDynamicSharedMemorySize, SMEM);
    cudaFuncSetAttribute(hmma_gemm<D_OUT, D_HID, 0>,
                         cudaFuncAttributeMaxDynamicSharedMemorySize, SMEM);

    // ---- build CSR (by dst) ----
    zero_deg<<<(N_NODES + 255) / 256, 256>>>();
    hist_dst<<<(N_EDGES + 255) / 256, 256>>>(dst);
    scan_deg<<<1, 1024>>>();
    scatter_edges<<<(N_EDGES + 255) / 256, 256>>>(src, dst);

    // ---- weight transpose + pre-split (tiny) ----
    transpose_split<<<(D_HID * D_IN + 255) / 256, 256>>>(W1, w1th, w1tl, D_IN, D_HID);
    transpose_split<<<(D_OUT * D_HID + 255) / 256, 256>>>(W2, w2th, w2tl, D_HID, D_OUT);

    const int agg_blocks = (N_NODES * 32 + 255) / 256;
    const int mblocks = (N_NODES + 127) / 128;   // 391

    // layer 1 aggregation -> split bf16 planes
    agg_csr<true, false, true><<<agg_blocks, 256>>>(
        cncpt, (const float4*)emb, nullptr, nullptr, a1h, a1l);

    // h1 = relu(agg1 @ W1 + b1) -> split bf16 planes
    hmma_gemm<D_HID, D_IN, 1><<<dim3(D_HID / 128, mblocks), 256, SMEM>>>(
        a1h, a1l, w1th, w1tl, b1, nullptr, h1h, h1l, N_NODES);

    // t2 = h1 @ W2 (GEMM commuted before aggregation) -> fp32
    hmma_gemm<D_OUT, D_HID, 0><<<dim3(D_OUT / 128, mblocks), 256, SMEM>>>(
        h1h, h1l, w2th, w2tl, nullptr, t2, nullptr, nullptr, N_NODES);

    // layer 2 aggregation + bias + relu into d_out
    agg_csr<false, true, false><<<agg_blocks, 256>>>(
        nullptr, (const float4*)t2, b2, (float4*)out, nullptr, nullptr);
}

// round 7
// speedup vs baseline: 1.8621x; 1.1540x over previous
#include <cuda_runtime.h>
#include <cuda_bf16.h>
#include <cstdint>

#define N_NODES 50000
#define N_EDGES 800000
#define D_IN 128
#define D_HID 256
#define D_OUT 128

// ---------------- scratch (static device arrays; no allocation) ----------------
__device__ __nv_bfloat16 g_a1h[(size_t)N_NODES * D_IN];    // agg1 hi   12.8 MB
__device__ __nv_bfloat16 g_a1l[(size_t)N_NODES * D_IN];    // agg1 lo
__device__ __nv_bfloat16 g_h1h[(size_t)N_NODES * D_HID];   // h1 hi     25.6 MB
__device__ __nv_bfloat16 g_h1l[(size_t)N_NODES * D_HID];   // h1 lo
__device__ float         g_t2[(size_t)N_NODES * D_OUT];    // 25.6 MB
__device__ __nv_bfloat16 g_w1th[D_HID * D_IN], g_w1tl[D_HID * D_IN];
__device__ __nv_bfloat16 g_w2th[D_OUT * D_HID], g_w2tl[D_OUT * D_HID];
__device__ int g_deg[N_NODES];
__device__ int g_off[N_NODES + 1];
__device__ int g_rank[N_EDGES];
__device__ int g_csr_src[N_EDGES];

// ================= small helpers =================
__device__ __forceinline__ uint32_t smem_u32(const void* p) {
    uint32_t a;
    asm("{ .reg .u64 t; cvta.to.shared.u64 t, %1; cvt.u32.u64 %0, t; }" : "=r"(a) : "l"(p));
    return a;
}

// split fp32 pair -> (hi bf16x2, lo bf16x2); low half of the b32 = first elem
__device__ __forceinline__ void split2(float a0, float a1, uint32_t& hi, uint32_t& lo) {
    asm("cvt.rn.bf16x2.f32 %0, %1, %2;" : "=r"(hi) : "f"(a1), "f"(a0));
    float h0 = __uint_as_float(hi << 16);
    float h1 = __uint_as_float(hi & 0xFFFF0000u);
    float l0 = a0 - h0, l1 = a1 - h1;
    asm("cvt.rn.bf16x2.f32 %0, %1, %2;" : "=r"(lo) : "f"(l1), "f"(l0));
}

__device__ __forceinline__ void ldsm_x4(uint32_t* r, uint32_t addr) {
    asm volatile("ldmatrix.sync.aligned.m8n8.x4.shared.b16 {%0,%1,%2,%3}, [%4];"
                 : "=r"(r[0]), "=r"(r[1]), "=r"(r[2]), "=r"(r[3]) : "r"(addr));
}

__device__ __forceinline__ void mma16816(float* d, const uint32_t* a, const uint32_t* b) {
    asm volatile("mma.sync.aligned.m16n8k16.row.col.f32.bf16.bf16.f32 "
                 "{%0,%1,%2,%3}, {%4,%5,%6,%7}, {%8,%9}, {%0,%1,%2,%3};"
                 : "+f"(d[0]), "+f"(d[1]), "+f"(d[2]), "+f"(d[3])
                 : "r"(a[0]), "r"(a[1]), "r"(a[2]), "r"(a[3]), "r"(b[0]), "r"(b[1]));
}

__device__ __forceinline__ void cp_async16(uint32_t dst, const void* src, int size) {
    asm volatile("cp.async.cg.shared.global [%0], [%1], 16, %2;"
                 :: "r"(dst), "l"(src), "r"(size) : "memory");
}

// swizzled smem byte offset within a plane: row stride 64B, chunk16 XOR (row>>1)&3
__device__ __forceinline__ uint32_t swz(int row, int chunk) {
    return (uint32_t)(row * 64 + ((chunk ^ ((row >> 1) & 3)) << 4));
}

// ================= CSR build =================
__global__ void zero_deg() {
    int i = blockIdx.x * blockDim.x + threadIdx.x;
    if (i < N_NODES) g_deg[i] = 0;
}
// histogram; also record each edge's within-bucket rank (atomic return value)
__global__ __launch_bounds__(256) void hist_dst(const int* __restrict__ dst) {
    int e = blockIdx.x * blockDim.x + threadIdx.x;
    if (e < N_EDGES) g_rank[e] = atomicAdd(&g_deg[dst[e]], 1);
}
__global__ __launch_bounds__(1024) void scan_deg() {
    __shared__ int sums[1024];
    const int CHUNK = (N_NODES + 1023) / 1024;
    int t = threadIdx.x;
    int lo = t * CHUNK;
    int hi = min(lo + CHUNK, N_NODES);
    int s = 0;
    for (int i = lo; i < hi; i++) s += g_deg[i];
    sums[t] = s;
    __syncthreads();
    for (int d = 1; d < 1024; d <<= 1) {
        int v = (t >= d) ? sums[t - d] : 0;
        __syncthreads();
        sums[t] += v;
        __syncthreads();
    }
    int running = sums[t] - s;
    for (int i = lo; i < hi; i++) {
        g_off[i] = running;
        running += g_deg[i];
    }
    if (t == 1023) g_off[N_NODES] = sums[1023];
}
// non-atomic scatter: position = off[dst] + precomputed rank
__global__ __launch_bounds__(256) void scatter_edges(
    const int* __restrict__ src, const int* __restrict__ dst)
{
    int e = blockIdx.x * blockDim.x + threadIdx.x;
    if (e >= N_EDGES) return;
    g_csr_src[g_off[dst[e]] + g_rank[e]] = src[e];
}

// ================= CSR aggregation: warp per node, no atomics =================
template<bool GATHER, bool EPI, bool SPLIT>
__global__ __launch_bounds__(256) void agg_csr(
    const int* __restrict__ cncpt, const float4* __restrict__ rows,
    const float* __restrict__ bias, float4* __restrict__ outf,
    __nv_bfloat16* __restrict__ oh, __nv_bfloat16* __restrict__ ol)
{
    int w = (blockIdx.x * blockDim.x + threadIdx.x) >> 5;
    if (w >= N_NODES) return;
    int lane = threadIdx.x & 31;
    int beg = g_off[w], end = g_off[w + 1];

    float4 acc = make_float4(0.f, 0.f, 0.f, 0.f);
    int j = beg;
    for (; j + 8 <= end; j += 8) {
        int s[8];
#pragma unroll
        for (int q = 0; q < 8; q++) s[q] = g_csr_src[j + q];
        if (GATHER) {
#pragma unroll
            for (int q = 0; q < 8; q++) s[q] = cncpt[s[q]];
        }
        float4 v[8];
#pragma unroll
        for (int q = 0; q < 8; q++) v[q] = rows[(size_t)s[q] * 32 + lane];
#pragma unroll
        for (int q = 0; q < 8; q++) {
            acc.x += v[q].x; acc.y += v[q].y; acc.z += v[q].z; acc.w += v[q].w;
        }
    }
    for (; j < end; j++) {
        int s = g_csr_src[j];
        if (GATHER) s = cncpt[s];
        float4 v = rows[(size_t)s * 32 + lane];
        acc.x += v.x; acc.y += v.y; acc.z += v.z; acc.w += v.w;
    }
    if (EPI) {
        float4 b = ((const float4*)bias)[lane];
        acc.x = fmaxf(acc.x + b.x, 0.f);
        acc.y = fmaxf(acc.y + b.y, 0.f);
        acc.z = fmaxf(acc.z + b.z, 0.f);
        acc.w = fmaxf(acc.w + b.w, 0.f);
    }
    if (SPLIT) {
        uint32_t h0, l0, h1, l1;
        split2(acc.x, acc.y, h0, l0);
        split2(acc.z, acc.w, h1, l1);
        size_t off = (size_t)w * 128 + lane * 4;
        *(uint2*)(oh + off) = make_uint2(h0, h1);
        *(uint2*)(ol + off) = make_uint2(l0, l1);
    } else {
        outf[(size_t)w * 32 + lane] = acc;
    }
}

// ================= weight transpose + split (tiny) =================
__global__ void transpose_split(const float* __restrict__ W,
                                __nv_bfloat16* __restrict__ Th,
                                __nv_bfloat16* __restrict__ Tl, int K, int N) {
    int i = blockIdx.x * blockDim.x + threadIdx.x;   // T is [N][K]
    if (i >= N * K) return;
    int n = i / K, k = i % K;
    float v = W[(size_t)k * N + n];
    __nv_bfloat16 h = __float2bfloat16_rn(v);
    Th[i] = h;
    Tl[i] = __float2bfloat16_rn(v - __bfloat162float(h));
}

// ================= HMMA split-bf16 GEMM, cp.async double-buffered =================
// C[M,NN] = (Ah+Al)[M,KK] @ (Bh+Bl)[NN,KK]^T via 3 products, fp32 accumulate.
// CTA tile BM x 128 (BM in {128, 64}), BK=32, 8 warps, 2-stage pipeline,
// swizzled 64B-stride smem. MODE 0: fp32 out. MODE 1: bias+relu, split bf16 out.
template<int BM, int NN, int KK, int MODE>
__global__ __launch_bounds__(256, 2) void hmma_gemm(
    const __nv_bfloat16* __restrict__ Ah, const __nv_bfloat16* __restrict__ Al,
    const __nv_bfloat16* __restrict__ Bh, const __nv_bfloat16* __restrict__ Bl,
    const float* __restrict__ bias, float* __restrict__ Cf,
    __nv_bfloat16* __restrict__ Ch, __nv_bfloat16* __restrict__ Cl, int M)
{
    constexpr int WMW = (BM == 128) ? 4 : 2;   // warps along M
    constexpr int WNW = 8 / WMW;               // warps along N
    constexpr int NW  = 128 / WNW;             // warp n-width (64 / 32)
    constexpr int NT  = NW / 8;                // n-tiles per warp (8 / 4)
    constexpr int APLANE_B = BM * 64;
    constexpr int BPLANE_B = 128 * 64;
    constexpr int STAGE_B  = 2 * APLANE_B + 2 * BPLANE_B;
    constexpr int ITERS    = (2 * BM + 256) * 4 / 256;   // 16B chunks per thread
    extern __shared__ __align__(16) char smem[];         // [2][STAGE_B]

    const int tid  = threadIdx.x;
    const int wid  = tid >> 5;
    const int lane = tid & 31;
    const int wm   = wid % WMW;
    const int wn   = wid / WMW;
    const int blockM = blockIdx.y * BM;
    const int blockN = blockIdx.x * 128;

    const uint32_t sb0 = smem_u32(smem);

    const int a_row = wm * 32 + (lane & 15);
    const int a_chk = lane >> 4;
    const int b_row = wn * NW + ((lane >> 4) << 3) + (lane & 7);
    const int b_chk = (lane >> 3) & 1;

    float acc[2][NT][4];
#pragma unroll
    for (int mt = 0; mt < 2; mt++)
#pragma unroll
        for (int j = 0; j < NT; j++)
#pragma unroll
            for (int q = 0; q < 4; q++) acc[mt][j][q] = 0.f;

    auto load_stage = [&](int s, int kc) {
        uint32_t sb = sb0 + (uint32_t)s * STAGE_B;
#pragma unroll
        for (int i = 0; i < ITERS; i++) {
            int g = i * 256 + tid;
            const __nv_bfloat16* src;
            uint32_t dst;
            int size = 16;
            if (g < 2 * BM * 4) {
                int p   = g >= BM * 4;              // 0=Ah, 1=Al
                int idx = g - p * BM * 4;
                int row = idx >> 2, c = idx & 3;
                int gm = blockM + row;
                int cm = gm < M ? gm : 0;
                if (gm >= M) size = 0;
                src = (p ? Al : Ah) + (size_t)cm * KK + kc + c * 8;
                dst = sb + (uint32_t)(p * APLANE_B) + swz(row, c);
            } else {
                int gb  = g - 8 * BM;
                int p   = gb >> 9;                  // 0=Bh, 1=Bl
                int idx = gb & 511;
                int row = idx >> 2, c = idx & 3;
                src = (p ? Bl : Bh) + (size_t)(blockN + row) * KK + kc + c * 8;
                dst = sb + (uint32_t)(2 * APLANE_B + p * BPLANE_B) + swz(row, c);
            }
            cp_async16(dst, src, size);
        }
        asm volatile("cp.async.commit_group;" ::: "memory");
    };

    constexpr int NC = KK / 32;
    load_stage(0, 0);

    for (int c = 0; c < NC; c++) {
        if (c + 1 < NC) {
            load_stage((c + 1) & 1, (c + 1) * 32);
            asm volatile("cp.async.wait_group 1;" ::: "memory");
        } else {
            asm volatile("cp.async.wait_group 0;" ::: "memory");
        }
        __syncthreads();

        const uint32_t base = sb0 + (uint32_t)(c & 1) * STAGE_B;
#pragma unroll
        for (int kh = 0; kh < 2; kh++) {
            uint32_t ah[2][4], al[2][4], bh[NT][2], bl[NT][2];
#pragma unroll
            for (int mt = 0; mt < 2; mt++) {
                uint32_t off = swz(a_row + mt * 16, kh * 2 + a_chk);
                ldsm_x4(ah[mt], base + off);
                ldsm_x4(al[mt], base + APLANE_B + off);
            }
#pragma unroll
            for (int jj = 0; jj < NT / 2; jj++) {
                uint32_t off = 2 * APLANE_B + swz(b_row + jj * 16, kh * 2 + b_chk);
                uint32_t t[4];
                ldsm_x4(t, base + off);
                bh[2 * jj][0] = t[0]; bh[2 * jj][1] = t[1];
                bh[2 * jj + 1][0] = t[2]; bh[2 * jj + 1][1] = t[3];
                ldsm_x4(t, base + BPLANE_B + off);
                bl[2 * jj][0] = t[0]; bl[2 * jj][1] = t[1];
                bl[2 * jj + 1][0] = t[2]; bl[2 * jj + 1][1] = t[3];
            }
#pragma unroll
            for (int mt = 0; mt < 2; mt++)
#pragma unroll
                for (int j = 0; j < NT; j++) mma16816(acc[mt][j], ah[mt], bh[j]);
#pragma unroll
            for (int mt = 0; mt < 2; mt++)
#pragma unroll
                for (int j = 0; j < NT; j++) mma16816(acc[mt][j], ah[mt], bl[j]);
#pragma unroll
            for (int mt = 0; mt < 2; mt++)
#pragma unroll
                for (int j = 0; j < NT; j++) mma16816(acc[mt][j], al[mt], bh[j]);
        }
        __syncthreads();
    }

    // ---- epilogue from C fragments ----
    const int m_base = blockM + wm * 32 + (lane >> 2);
    const int n_base = blockN + wn * NW + 2 * (lane & 3);
#pragma unroll
    for (int mt = 0; mt < 2; mt++) {
#pragma unroll
        for (int j = 0; j < NT; j++) {
            int n = n_base + 8 * j;
            float2 v0 = make_float2(acc[mt][j][0], acc[mt][j][1]);
            float2 v1 = make_float2(acc[mt][j][2], acc[mt][j][3]);
            int m = m_base + mt * 16;
            if (MODE == 1) {
                float bb0 = bias[n], bb1 = bias[n + 1];
                v0.x = fmaxf(v0.x + bb0, 0.f); v0.y = fmaxf(v0.y + bb1, 0.f);
                v1.x = fmaxf(v1.x + bb0, 0.f); v1.y = fmaxf(v1.y + bb1, 0.f);
                uint32_t h, l;
                if (m < M) {
                    split2(v0.x, v0.y, h, l);
                    *(uint32_t*)(Ch + (size_t)m * NN + n) = h;
                    *(uint32_t*)(Cl + (size_t)m * NN + n) = l;
                }
                if (m + 8 < M) {
                    split2(v1.x, v1.y, h, l);
                    *(uint32_t*)(Ch + (size_t)(m + 8) * NN + n) = h;
                    *(uint32_t*)(Cl + (size_t)(m + 8) * NN + n) = l;
                }
            } else {
                if (m < M)     *(float2*)(Cf + (size_t)m * NN + n)       = v0;
                if (m + 8 < M) *(float2*)(Cf + (size_t)(m + 8) * NN + n) = v1;
            }
        }
    }
}

// ---------------- launch ----------------
extern "C" void kernel_launch(void* const* d_in, const int* in_sizes, int n_in,
                              void* d_out, int out_size) {
    const int*   cncpt = (const int*)d_in[0];
    const int*   src   = (const int*)d_in[1];
    const int*   dst   = (const int*)d_in[2];
    const float* emb   = (const float*)d_in[3];
    const float* W1    = (const float*)d_in[4];
    const float* b1    = (const float*)d_in[5];
    const float* W2    = (const float*)d_in[6];
    const float* b2    = (const float*)d_in[7];
    float* out = (float*)d_out;

    __nv_bfloat16 *a1h, *a1l, *h1h, *h1l, *w1th, *w1tl, *w2th, *w2tl;
    float *t2;
    cudaGetSymbolAddress((void**)&a1h,  g_a1h);
    cudaGetSymbolAddress((void**)&a1l,  g_a1l);
    cudaGetSymbolAddress((void**)&h1h,  g_h1h);
    cudaGetSymbolAddress((void**)&h1l,  g_h1l);
    cudaGetSymbolAddress((void**)&t2,   g_t2);
    cudaGetSymbolAddress((void**)&w1th, g_w1th);
    cudaGetSymbolAddress((void**)&w1tl, g_w1tl);
    cudaGetSymbolAddress((void**)&w2th, g_w2th);
    cudaGetSymbolAddress((void**)&w2tl, g_w2tl);

    const int SMEM1 = 2 * (2 * 128 * 64 + 2 * 128 * 64);   // 65536 B (BM=128)
    const int SMEM2 = 2 * (2 * 64 * 64 + 2 * 128 * 64);    // 49152 B (BM=64)
    cudaFuncSetAttribute(hmma_gemm<128, D_HID, D_IN, 1>,
                         cudaFuncAttributeMaxDynamicSharedMemorySize, SMEM1);
    cudaFuncSetAttribute(hmma_gemm<64, D_OUT, D_HID, 0>,
                         cudaFuncAttributeMaxDynamicSharedMemorySize, SMEM2);

    // ---- build CSR (by dst) ----
    zero_deg<<<(N_NODES + 255) / 256, 256>>>();
    hist_dst<<<(N_EDGES + 255) / 256, 256>>>(dst);
    scan_deg<<<1, 1024>>>();
    scatter_edges<<<(N_EDGES + 255) / 256, 256>>>(src, dst);

    // ---- weight transpose + pre-split (tiny) ----
    transpose_split<<<(D_HID * D_IN + 255) / 256, 256>>>(W1, w1th, w1tl, D_IN, D_HID);
    transpose_split<<<(D_OUT * D_HID + 255) / 256, 256>>>(W2, w2th, w2tl, D_HID, D_OUT);

    const int agg_blocks = (N_NODES * 32 + 255) / 256;

    // layer 1 aggregation -> split bf16 planes
    agg_csr<true, false, true><<<agg_blocks, 256>>>(
        cncpt, (const float4*)emb, nullptr, nullptr, a1h, a1l);

    // h1 = relu(agg1 @ W1 + b1) -> split bf16 planes  (tiles 128x128)
    hmma_gemm<128, D_HID, D_IN, 1><<<dim3(D_HID / 128, (N_NODES + 127) / 128), 256, SMEM1>>>(
        a1h, a1l, w1th, w1tl, b1, nullptr, h1h, h1l, N_NODES);

    // t2 = h1 @ W2 (GEMM commuted before aggregation) -> fp32  (tiles 64x128)
    hmma_gemm<64, D_OUT, D_HID, 0><<<dim3(1, (N_NODES + 63) / 64), 256, SMEM2>>>(
        h1h, h1l, w2th, w2tl, nullptr, t2, nullptr, nullptr, N_NODES);

    // layer 2 aggregation + bias + relu into d_out
    agg_csr<false, true, false><<<agg_blocks, 256>>>(
        nullptr, (const float4*)t2, b2, (float4*)out, nullptr, nullptr);
}